// round 1
// baseline (speedup 1.0000x reference)
#include <cuda_runtime.h>
#include <cuda_bf16.h>
#include <math.h>

// ---------------------------------------------------------------------------
// MiniTransformer forward: B=16, T=1024, D=512, H=8, HS=64, L=6, FF=2048, V=96
// Output: logits [16384, 96] (fp32) followed by scalar loss.
// ---------------------------------------------------------------------------

#define B_   16
#define T_   1024
#define D_   512
#define H_   8
#define HS_  64
#define L_   6
#define FF_  2048
#define V_   96
#define BT_  (B_ * T_)

// ------------------------- device scratch (no mallocs) ---------------------
__device__ float  g_x   [BT_ * D_];        // residual stream
__device__ float  g_h   [BT_ * D_];        // LN output
__device__ float  g_qkv [BT_ * 3 * D_];    // packed q|k|v per token
__device__ float  g_o   [BT_ * D_];        // attention output (concat heads)
__device__ float  g_ff  [BT_ * FF_];       // FFN hidden
__device__ float  g_wp  [L_ * D_ * 3 * D_];// packed QKV weights [l][d][3D]
__device__ double g_loss;

// ------------------------- small kernels -----------------------------------
__global__ void zero_loss_kernel(double* a) { *a = 0.0; }

__global__ void pack_qkv_kernel(const float* __restrict__ Wq,
                                const float* __restrict__ Wk,
                                const float* __restrict__ Wv,
                                float* __restrict__ out) {
    int i = blockIdx.x * blockDim.x + threadIdx.x;       // over L*D*3D
    if (i >= L_ * D_ * 3 * D_) return;
    int c = i % (3 * D_);
    int d = (i / (3 * D_)) % D_;
    int l = i / (3 * D_ * D_);
    int sel = c >> 9;              // 0=q 1=k 2=v (512 cols each)
    int hk  = c & 511;
    int h   = hk >> 6;
    int k   = hk & 63;
    const float* W = (sel == 0) ? Wq : (sel == 1) ? Wk : Wv;
    out[i] = W[(((size_t)l * H_ + h) * D_ + d) * HS_ + k];
}

__global__ void embed_kernel(const int* __restrict__ idx,
                             const float* __restrict__ tok,
                             const float* __restrict__ pos,
                             float* __restrict__ x) {
    int i = blockIdx.x * blockDim.x + threadIdx.x;       // over BT*D
    if (i >= BT_ * D_) return;
    int d  = i & (D_ - 1);
    int bt = i >> 9;
    int t  = bt & (T_ - 1);
    x[i] = tok[(size_t)idx[bt] * D_ + d] + pos[t * D_ + d];
}

// One block per row; D=512, 256 threads, 2 elems/thread.
__global__ __launch_bounds__(256) void ln_kernel(const float* __restrict__ x,
                                                 const float* __restrict__ s,
                                                 const float* __restrict__ b,
                                                 float* __restrict__ out) {
    int row = blockIdx.x;
    int t   = threadIdx.x;
    const float* xr = x + (size_t)row * D_;
    float v0 = xr[t], v1 = xr[t + 256];

    float sum = v0 + v1;
    #pragma unroll
    for (int o = 16; o; o >>= 1) sum += __shfl_xor_sync(0xffffffffu, sum, o);
    __shared__ float red1[8], red2[8];
    if ((t & 31) == 0) red1[t >> 5] = sum;
    __syncthreads();
    float mean = 0.f;
    #pragma unroll
    for (int i = 0; i < 8; i++) mean += red1[i];
    mean *= (1.0f / D_);

    float d0 = v0 - mean, d1 = v1 - mean;
    float vs = d0 * d0 + d1 * d1;
    #pragma unroll
    for (int o = 16; o; o >>= 1) vs += __shfl_xor_sync(0xffffffffu, vs, o);
    if ((t & 31) == 0) red2[t >> 5] = vs;
    __syncthreads();
    float var = 0.f;
    #pragma unroll
    for (int i = 0; i < 8; i++) var += red2[i];
    var *= (1.0f / D_);

    float inv = rsqrtf(var + 1e-5f);
    float* orow = out + (size_t)row * D_;
    orow[t]       = d0 * inv * s[t]       + b[t];
    orow[t + 256] = d1 * inv * s[t + 256] + b[t + 256];
}

// ------------------------- SGEMM 128x128x8, 256 threads, 8x8 microtile -----
// C[M,N] = A[M,K] * B[K,N]  (+bias, +relu, +residual per `mode`)
// mode: 0 = none, 1 = +bias, 2 = +bias,relu, 3 = +bias,+res
// Requires: M % 128 == 0, K % 8 == 0. N guarded.
__global__ __launch_bounds__(256) void sgemm_kernel(
    const float* __restrict__ A, const float* __restrict__ Bm,
    const float* __restrict__ bias, const float* __restrict__ res,
    float* __restrict__ C, int M, int N, int K, int mode)
{
    __shared__ float As[8][128];
    __shared__ float Bs[8][128];
    int tid  = threadIdx.x;
    int trow = tid >> 4;            // 0..15
    int tcol = tid & 15;            // 0..15
    int arow = tid >> 1;            // 0..127
    int acol = (tid & 1) << 2;      // 0 or 4
    int brow = tid >> 5;            // 0..7
    int bcol = (tid & 31) << 2;     // 0..124
    long Abase = (long)(blockIdx.y * 128 + arow) * K + acol;
    int  gbc   = blockIdx.x * 128 + bcol;

    float acc[8][8];
    #pragma unroll
    for (int i = 0; i < 8; i++)
        #pragma unroll
        for (int j = 0; j < 8; j++) acc[i][j] = 0.f;

    for (int k0 = 0; k0 < K; k0 += 8) {
        float4 av = *(const float4*)(A + Abase + k0);
        As[acol + 0][arow] = av.x;
        As[acol + 1][arow] = av.y;
        As[acol + 2][arow] = av.z;
        As[acol + 3][arow] = av.w;

        const float* Bp = Bm + (long)(k0 + brow) * N;
        float4 bv = make_float4(0.f, 0.f, 0.f, 0.f);
        if (gbc + 3 < N) {
            bv = *(const float4*)(Bp + gbc);
        } else {
            if (gbc + 0 < N) bv.x = Bp[gbc + 0];
            if (gbc + 1 < N) bv.y = Bp[gbc + 1];
            if (gbc + 2 < N) bv.z = Bp[gbc + 2];
        }
        *(float4*)&Bs[brow][bcol] = bv;
        __syncthreads();

        #pragma unroll
        for (int kk = 0; kk < 8; kk++) {
            float4 a0 = *(const float4*)&As[kk][trow * 8];
            float4 a1 = *(const float4*)&As[kk][trow * 8 + 4];
            float4 b0 = *(const float4*)&Bs[kk][tcol * 8];
            float4 b1 = *(const float4*)&Bs[kk][tcol * 8 + 4];
            float ar[8] = {a0.x, a0.y, a0.z, a0.w, a1.x, a1.y, a1.z, a1.w};
            float br[8] = {b0.x, b0.y, b0.z, b0.w, b1.x, b1.y, b1.z, b1.w};
            #pragma unroll
            for (int i = 0; i < 8; i++)
                #pragma unroll
                for (int j = 0; j < 8; j++)
                    acc[i][j] += ar[i] * br[j];
        }
        __syncthreads();
    }

    int row0 = blockIdx.y * 128 + trow * 8;
    int col0 = blockIdx.x * 128 + tcol * 8;
    #pragma unroll
    for (int i = 0; i < 8; i++) {
        long rbase = (long)(row0 + i) * N;
        #pragma unroll
        for (int j = 0; j < 8; j++) {
            int c = col0 + j;
            if (c < N) {
                float v = acc[i][j];
                if (mode >= 1) v += bias[c];
                if (mode == 2) v = fmaxf(v, 0.f);
                if (mode == 3) v += res[rbase + c];
                C[rbase + c] = v;
            }
        }
    }
}

// ------------------------- flash attention ---------------------------------
// QKV [BT, 1536] per-token q|k|v; heads at h*64 within each 512 chunk.
// grid: (T/128, B*H), block 128 threads, 1 query per thread.
__global__ __launch_bounds__(128) void attn_kernel(const float* __restrict__ QKV,
                                                   float* __restrict__ O) {
    const int KT = 32;
    int b = blockIdx.y >> 3;
    int h = blockIdx.y & 7;
    int q_idx = blockIdx.x * 128 + threadIdx.x;
    const float scale = 0.04419417382415922f;  // 1/sqrt(512)

    const float* qrow = QKV + ((size_t)(b * T_ + q_idx)) * (3 * D_) + h * HS_;
    float q[HS_];
    #pragma unroll
    for (int d = 0; d < HS_; d++) q[d] = qrow[d] * scale;
    float o[HS_];
    #pragma unroll
    for (int d = 0; d < HS_; d++) o[d] = 0.f;
    float m = -1e30f, l = 0.f;

    __shared__ float Ks[KT][HS_];
    __shared__ float Vs[KT][HS_];

    int kend = blockIdx.x * 128 + 128;
    for (int k0 = 0; k0 < kend; k0 += KT) {
        __syncthreads();
        for (int i = threadIdx.x; i < KT * (HS_ / 4); i += 128) {
            int r = i >> 4, c = (i & 15) << 2;
            const float* base = QKV + ((size_t)(b * T_ + k0 + r)) * (3 * D_) + h * HS_ + c;
            *(float4*)&Ks[r][c] = *(const float4*)(base + D_);
            *(float4*)&Vs[r][c] = *(const float4*)(base + 2 * D_);
        }
        __syncthreads();

        float s[KT];
        float mnew = m;
        #pragma unroll
        for (int j = 0; j < KT; j++) {
            float acc = 0.f;
            #pragma unroll
            for (int d = 0; d < HS_; d++) acc += q[d] * Ks[j][d];
            s[j] = (k0 + j <= q_idx) ? acc : -1e30f;
            mnew = fmaxf(mnew, s[j]);
        }
        float corr = __expf(m - mnew);
        l *= corr;
        #pragma unroll
        for (int d = 0; d < HS_; d++) o[d] *= corr;
        #pragma unroll
        for (int j = 0; j < KT; j++) {
            float p = __expf(s[j] - mnew);
            l += p;
            #pragma unroll
            for (int d = 0; d < HS_; d++) o[d] += p * Vs[j][d];
        }
        m = mnew;
    }

    float inv = 1.f / l;
    float* orow = O + ((size_t)(b * T_ + q_idx)) * D_ + h * HS_;
    #pragma unroll
    for (int d = 0; d < HS_; d++) orow[d] = o[d] * inv;
}

// ------------------------- loss --------------------------------------------
// One warp per row of logits [BT, 96]; 3 values/lane.
__global__ __launch_bounds__(256) void loss_kernel(const float* __restrict__ logits,
                                                   const int* __restrict__ targets,
                                                   double* __restrict__ acc) {
    int warp = (blockIdx.x * blockDim.x + threadIdx.x) >> 5;
    int lane = threadIdx.x & 31;
    const float* lr = logits + (size_t)warp * V_;
    float v0 = lr[lane], v1 = lr[lane + 32], v2 = lr[lane + 64];
    float m = fmaxf(v0, fmaxf(v1, v2));
    #pragma unroll
    for (int o = 16; o; o >>= 1) m = fmaxf(m, __shfl_xor_sync(0xffffffffu, m, o));
    float se = expf(v0 - m) + expf(v1 - m) + expf(v2 - m);
    #pragma unroll
    for (int o = 16; o; o >>= 1) se += __shfl_xor_sync(0xffffffffu, se, o);

    __shared__ float part[8];
    if (lane == 0) part[threadIdx.x >> 5] = lr[targets[warp]] - m - logf(se);
    __syncthreads();
    if (threadIdx.x == 0) {
        float s = 0.f;
        #pragma unroll
        for (int i = 0; i < 8; i++) s += part[i];
        atomicAdd(acc, (double)s);
    }
}

__global__ void finalize_loss_kernel(float* out, const double* acc) {
    out[(size_t)BT_ * V_] = (float)(-(*acc) / (double)BT_);
}

// ------------------------- launcher ----------------------------------------
extern "C" void kernel_launch(void* const* d_in, const int* in_sizes, int n_in,
                              void* d_out, int out_size) {
    const int*   idx     = (const int*)  d_in[0];
    const int*   targets = (const int*)  d_in[1];
    const float* tok     = (const float*)d_in[2];
    const float* pos     = (const float*)d_in[3];
    const float* Wq      = (const float*)d_in[4];
    const float* Wk      = (const float*)d_in[5];
    const float* Wv      = (const float*)d_in[6];
    const float* Wproj   = (const float*)d_in[7];
    const float* bproj   = (const float*)d_in[8];
    const float* W1      = (const float*)d_in[9];
    const float* b1      = (const float*)d_in[10];
    const float* W2      = (const float*)d_in[11];
    const float* b2      = (const float*)d_in[12];
    const float* ln1_s   = (const float*)d_in[13];
    const float* ln1_b   = (const float*)d_in[14];
    const float* ln2_s   = (const float*)d_in[15];
    const float* ln2_b   = (const float*)d_in[16];
    const float* lnf_s   = (const float*)d_in[17];
    const float* lnf_b   = (const float*)d_in[18];
    const float* Wout    = (const float*)d_in[19];
    const float* bout    = (const float*)d_in[20];
    float* out = (float*)d_out;

    float *x, *h, *qkv, *o, *ff, *wp;
    double* lossAcc;
    cudaGetSymbolAddress((void**)&x,   g_x);
    cudaGetSymbolAddress((void**)&h,   g_h);
    cudaGetSymbolAddress((void**)&qkv, g_qkv);
    cudaGetSymbolAddress((void**)&o,   g_o);
    cudaGetSymbolAddress((void**)&ff,  g_ff);
    cudaGetSymbolAddress((void**)&wp,  g_wp);
    cudaGetSymbolAddress((void**)&lossAcc, g_loss);

    // pack QKV weights: [L][H][D][HS] -> [L][D][3D]
    {
        int total = L_ * D_ * 3 * D_;
        pack_qkv_kernel<<<(total + 255) / 256, 256>>>(Wq, Wk, Wv, wp);
    }
    // embedding
    {
        int total = BT_ * D_;
        embed_kernel<<<(total + 255) / 256, 256>>>(idx, tok, pos, x);
    }

    const int MT = BT_ / 128;  // 128 M-tiles
    for (int l = 0; l < L_; l++) {
        // LN1
        ln_kernel<<<BT_, 256>>>(x, ln1_s + l * D_, ln1_b + l * D_, h);
        // QKV: [BT,512] x [512,1536]
        sgemm_kernel<<<dim3(12, MT), 256>>>(h, wp + (size_t)l * D_ * 3 * D_,
                                            nullptr, nullptr, qkv,
                                            BT_, 3 * D_, D_, 0);
        // attention
        attn_kernel<<<dim3(T_ / 128, B_ * H_), 128>>>(qkv, o);
        // proj + bias + residual into x
        sgemm_kernel<<<dim3(4, MT), 256>>>(o, Wproj + (size_t)l * D_ * D_,
                                           bproj + l * D_, x, x,
                                           BT_, D_, D_, 3);
        // LN2
        ln_kernel<<<BT_, 256>>>(x, ln2_s + l * D_, ln2_b + l * D_, h);
        // FF1 + bias + relu
        sgemm_kernel<<<dim3(16, MT), 256>>>(h, W1 + (size_t)l * D_ * FF_,
                                            b1 + l * FF_, nullptr, ff,
                                            BT_, FF_, D_, 2);
        // FF2 + bias + residual into x
        sgemm_kernel<<<dim3(4, MT), 256>>>(ff, W2 + (size_t)l * FF_ * D_,
                                           b2 + l * D_, x, x,
                                           BT_, D_, FF_, 3);
    }

    // final LN
    ln_kernel<<<BT_, 256>>>(x, lnf_s, lnf_b, h);
    // logits: [BT,512] x [512,96] + bout -> d_out
    sgemm_kernel<<<dim3(1, MT), 256>>>(h, Wout, bout, nullptr, out,
                                       BT_, V_, D_, 1);

    // loss
    if (out_size > BT_ * V_) {
        zero_loss_kernel<<<1, 1>>>(lossAcc);
        loss_kernel<<<BT_ / 8, 256>>>(out, targets, lossAcc);
        finalize_loss_kernel<<<1, 1>>>(out, lossAcc);
    }
}

// round 2
// speedup vs baseline: 1.0343x; 1.0343x over previous
#include <cuda_runtime.h>
#include <cuda_bf16.h>
#include <math.h>

// ---------------------------------------------------------------------------
// MiniTransformer forward: B=16, T=1024, D=512, H=8, HS=64, L=6, FF=2048, V=96
// Output: logits [16384, 96] (fp32) followed by scalar loss.
// ---------------------------------------------------------------------------

#define B_   16
#define T_   1024
#define D_   512
#define H_   8
#define HS_  64
#define L_   6
#define FF_  2048
#define V_   96
#define BT_  (B_ * T_)

// ------------------------- device scratch (no mallocs) ---------------------
__device__ float  g_x   [BT_ * D_];        // residual stream
__device__ float  g_h   [BT_ * D_];        // LN output
__device__ float  g_qkv [BT_ * 3 * D_];    // packed q|k|v per token
__device__ float  g_o   [BT_ * D_];        // attention output (concat heads)
__device__ float  g_ff  [BT_ * FF_];       // FFN hidden
__device__ float  g_wp  [L_ * D_ * 3 * D_];// packed QKV weights [l][d][3D]
__device__ double g_loss;

// ------------------------- small kernels -----------------------------------
__global__ void zero_loss_kernel(double* a) { *a = 0.0; }

__global__ void pack_qkv_kernel(const float* __restrict__ Wq,
                                const float* __restrict__ Wk,
                                const float* __restrict__ Wv,
                                float* __restrict__ out) {
    int i = blockIdx.x * blockDim.x + threadIdx.x;       // over L*D*3D
    if (i >= L_ * D_ * 3 * D_) return;
    int c = i % (3 * D_);
    int d = (i / (3 * D_)) % D_;
    int l = i / (3 * D_ * D_);
    int sel = c >> 9;              // 0=q 1=k 2=v (512 cols each)
    int hk  = c & 511;
    int h   = hk >> 6;
    int k   = hk & 63;
    const float* W = (sel == 0) ? Wq : (sel == 1) ? Wk : Wv;
    out[i] = W[(((size_t)l * H_ + h) * D_ + d) * HS_ + k];
}

__global__ void embed_kernel(const int* __restrict__ idx,
                             const float* __restrict__ tok,
                             const float* __restrict__ pos,
                             float* __restrict__ x) {
    int i = blockIdx.x * blockDim.x + threadIdx.x;       // over BT*D
    if (i >= BT_ * D_) return;
    int d  = i & (D_ - 1);
    int bt = i >> 9;
    int t  = bt & (T_ - 1);
    x[i] = tok[(size_t)idx[bt] * D_ + d] + pos[t * D_ + d];
}

// One block per row; D=512, 256 threads, 2 elems/thread.
__global__ __launch_bounds__(256) void ln_kernel(const float* __restrict__ x,
                                                 const float* __restrict__ s,
                                                 const float* __restrict__ b,
                                                 float* __restrict__ out) {
    int row = blockIdx.x;
    int t   = threadIdx.x;
    const float* xr = x + (size_t)row * D_;
    float v0 = xr[t], v1 = xr[t + 256];

    float sum = v0 + v1;
    #pragma unroll
    for (int o = 16; o; o >>= 1) sum += __shfl_xor_sync(0xffffffffu, sum, o);
    __shared__ float red1[8], red2[8];
    if ((t & 31) == 0) red1[t >> 5] = sum;
    __syncthreads();
    float mean = 0.f;
    #pragma unroll
    for (int i = 0; i < 8; i++) mean += red1[i];
    mean *= (1.0f / D_);

    float d0 = v0 - mean, d1 = v1 - mean;
    float vs = d0 * d0 + d1 * d1;
    #pragma unroll
    for (int o = 16; o; o >>= 1) vs += __shfl_xor_sync(0xffffffffu, vs, o);
    if ((t & 31) == 0) red2[t >> 5] = vs;
    __syncthreads();
    float var = 0.f;
    #pragma unroll
    for (int i = 0; i < 8; i++) var += red2[i];
    var *= (1.0f / D_);

    float inv = rsqrtf(var + 1e-5f);
    float* orow = out + (size_t)row * D_;
    orow[t]       = d0 * inv * s[t]       + b[t];
    orow[t + 256] = d1 * inv * s[t + 256] + b[t + 256];
}

// ------------------------- SGEMM 128x128x16, double buffered ---------------
// C[M,N] = A[M,K] * B[K,N]  (+bias, +relu, +residual per `mode`)
// mode: 0 = none, 1 = +bias, 2 = +bias,relu, 3 = +bias,+res
// Requires: M % 128 == 0, K % 16 == 0. N guarded.
#define KT_ 16
#define ASTRIDE_ 132   // padded: 132*4 = 528 bytes, 16B-aligned rows; STS 2-way max

__global__ __launch_bounds__(256) void sgemm_kernel(
    const float* __restrict__ A, const float* __restrict__ Bm,
    const float* __restrict__ bias, const float* __restrict__ res,
    float* __restrict__ C, int M, int N, int K, int mode)
{
    __shared__ float As[2][KT_][ASTRIDE_];   // transposed: [k][m]
    __shared__ float Bs[2][KT_][128];        // [k][n]

    int tid  = threadIdx.x;
    int trow = tid >> 4;            // 0..15
    int tcol = tid & 15;            // 0..15

    // A loads: 128 rows x 16 k-cols = 512 float4; 2 per thread
    int arow  = tid >> 2;           // 0..63  (second: +64)
    int acol  = (tid & 3) << 2;     // 0,4,8,12
    // B loads: 16 rows x 128 cols = 512 float4; 2 per thread
    int brow  = tid >> 5;           // 0..7   (second: +8)
    int bcol  = (tid & 31) << 2;    // 0..124

    const float* Ap = A + (size_t)(blockIdx.y * 128 + arow) * K + acol;
    const float* Ap2 = Ap + (size_t)64 * K;
    int gbc = blockIdx.x * 128 + bcol;

    float acc[8][8];
    #pragma unroll
    for (int i = 0; i < 8; i++)
        #pragma unroll
        for (int j = 0; j < 8; j++) acc[i][j] = 0.f;

    float4 pa0, pa1, pb0, pb1;

    // ---- load stage 0 ----
    {
        pa0 = *(const float4*)(Ap);
        pa1 = *(const float4*)(Ap2);
        const float* Bp0 = Bm + (size_t)brow * N;
        const float* Bp1 = Bm + (size_t)(brow + 8) * N;
        if (gbc + 3 < N) {
            pb0 = *(const float4*)(Bp0 + gbc);
            pb1 = *(const float4*)(Bp1 + gbc);
        } else {
            pb0 = make_float4(0.f, 0.f, 0.f, 0.f);
            pb1 = make_float4(0.f, 0.f, 0.f, 0.f);
            if (gbc + 0 < N) { pb0.x = Bp0[gbc + 0]; pb1.x = Bp1[gbc + 0]; }
            if (gbc + 1 < N) { pb0.y = Bp0[gbc + 1]; pb1.y = Bp1[gbc + 1]; }
            if (gbc + 2 < N) { pb0.z = Bp0[gbc + 2]; pb1.z = Bp1[gbc + 2]; }
        }
    }
    // store stage 0
    {
        As[0][acol + 0][arow] = pa0.x; As[0][acol + 1][arow] = pa0.y;
        As[0][acol + 2][arow] = pa0.z; As[0][acol + 3][arow] = pa0.w;
        As[0][acol + 0][arow + 64] = pa1.x; As[0][acol + 1][arow + 64] = pa1.y;
        As[0][acol + 2][arow + 64] = pa1.z; As[0][acol + 3][arow + 64] = pa1.w;
        *(float4*)&Bs[0][brow][bcol]     = pb0;
        *(float4*)&Bs[0][brow + 8][bcol] = pb1;
    }
    __syncthreads();

    int nstage = K / KT_;
    int cur = 0;
    for (int s = 0; s < nstage; s++) {
        // prefetch next stage into registers
        if (s + 1 < nstage) {
            int k0 = (s + 1) * KT_;
            pa0 = *(const float4*)(Ap + k0);
            pa1 = *(const float4*)(Ap2 + k0);
            const float* Bp0 = Bm + (size_t)(k0 + brow) * N;
            const float* Bp1 = Bm + (size_t)(k0 + brow + 8) * N;
            if (gbc + 3 < N) {
                pb0 = *(const float4*)(Bp0 + gbc);
                pb1 = *(const float4*)(Bp1 + gbc);
            } else {
                pb0 = make_float4(0.f, 0.f, 0.f, 0.f);
                pb1 = make_float4(0.f, 0.f, 0.f, 0.f);
                if (gbc + 0 < N) { pb0.x = Bp0[gbc + 0]; pb1.x = Bp1[gbc + 0]; }
                if (gbc + 1 < N) { pb0.y = Bp0[gbc + 1]; pb1.y = Bp1[gbc + 1]; }
                if (gbc + 2 < N) { pb0.z = Bp0[gbc + 2]; pb1.z = Bp1[gbc + 2]; }
            }
        }

        // compute current stage
        #pragma unroll
        for (int kk = 0; kk < KT_; kk++) {
            float4 a0 = *(const float4*)&As[cur][kk][trow * 8];
            float4 a1 = *(const float4*)&As[cur][kk][trow * 8 + 4];
            float4 b0 = *(const float4*)&Bs[cur][kk][tcol * 8];
            float4 b1 = *(const float4*)&Bs[cur][kk][tcol * 8 + 4];
            float ar[8] = {a0.x, a0.y, a0.z, a0.w, a1.x, a1.y, a1.z, a1.w};
            float br[8] = {b0.x, b0.y, b0.z, b0.w, b1.x, b1.y, b1.z, b1.w};
            #pragma unroll
            for (int i = 0; i < 8; i++)
                #pragma unroll
                for (int j = 0; j < 8; j++)
                    acc[i][j] += ar[i] * br[j];
        }

        // store prefetched regs into the other buffer
        if (s + 1 < nstage) {
            int nxt = cur ^ 1;
            As[nxt][acol + 0][arow] = pa0.x; As[nxt][acol + 1][arow] = pa0.y;
            As[nxt][acol + 2][arow] = pa0.z; As[nxt][acol + 3][arow] = pa0.w;
            As[nxt][acol + 0][arow + 64] = pa1.x; As[nxt][acol + 1][arow + 64] = pa1.y;
            As[nxt][acol + 2][arow + 64] = pa1.z; As[nxt][acol + 3][arow + 64] = pa1.w;
            *(float4*)&Bs[nxt][brow][bcol]     = pb0;
            *(float4*)&Bs[nxt][brow + 8][bcol] = pb1;
            __syncthreads();
            cur = nxt;
        }
    }

    int row0 = blockIdx.y * 128 + trow * 8;
    int col0 = blockIdx.x * 128 + tcol * 8;
    #pragma unroll
    for (int i = 0; i < 8; i++) {
        size_t rbase = (size_t)(row0 + i) * N;
        #pragma unroll
        for (int j = 0; j < 8; j++) {
            int c = col0 + j;
            if (c < N) {
                float v = acc[i][j];
                if (mode >= 1) v += bias[c];
                if (mode == 2) v = fmaxf(v, 0.f);
                if (mode == 3) v += res[rbase + c];
                C[rbase + c] = v;
            }
        }
    }
}

// ------------------------- flash attention ---------------------------------
// QKV [BT, 1536] per-token q|k|v; heads at h*64 within each 512 chunk.
// grid: (T/128, B*H), block 128 threads, 1 query per thread.
__global__ __launch_bounds__(128) void attn_kernel(const float* __restrict__ QKV,
                                                   float* __restrict__ O) {
    const int KT = 32;
    int b = blockIdx.y >> 3;
    int h = blockIdx.y & 7;
    int q_idx = blockIdx.x * 128 + threadIdx.x;
    const float scale = 0.04419417382415922f;  // 1/sqrt(512)

    const float* qrow = QKV + ((size_t)(b * T_ + q_idx)) * (3 * D_) + h * HS_;
    float q[HS_];
    #pragma unroll
    for (int d = 0; d < HS_; d++) q[d] = qrow[d] * scale;
    float o[HS_];
    #pragma unroll
    for (int d = 0; d < HS_; d++) o[d] = 0.f;
    float m = -1e30f, l = 0.f;

    __shared__ float Ks[KT][HS_];
    __shared__ float Vs[KT][HS_];

    int kend = blockIdx.x * 128 + 128;
    for (int k0 = 0; k0 < kend; k0 += KT) {
        __syncthreads();
        for (int i = threadIdx.x; i < KT * (HS_ / 4); i += 128) {
            int r = i >> 4, c = (i & 15) << 2;
            const float* base = QKV + ((size_t)(b * T_ + k0 + r)) * (3 * D_) + h * HS_ + c;
            *(float4*)&Ks[r][c] = *(const float4*)(base + D_);
            *(float4*)&Vs[r][c] = *(const float4*)(base + 2 * D_);
        }
        __syncthreads();

        float s[KT];
        float mnew = m;
        #pragma unroll
        for (int j = 0; j < KT; j++) {
            float acc = 0.f;
            #pragma unroll
            for (int d = 0; d < HS_; d++) acc += q[d] * Ks[j][d];
            s[j] = (k0 + j <= q_idx) ? acc : -1e30f;
            mnew = fmaxf(mnew, s[j]);
        }
        float corr = __expf(m - mnew);
        l *= corr;
        #pragma unroll
        for (int d = 0; d < HS_; d++) o[d] *= corr;
        #pragma unroll
        for (int j = 0; j < KT; j++) {
            float p = __expf(s[j] - mnew);
            l += p;
            #pragma unroll
            for (int d = 0; d < HS_; d++) o[d] += p * Vs[j][d];
        }
        m = mnew;
    }

    float inv = 1.f / l;
    float* orow = O + ((size_t)(b * T_ + q_idx)) * D_ + h * HS_;
    #pragma unroll
    for (int d = 0; d < HS_; d++) orow[d] = o[d] * inv;
}

// ------------------------- loss --------------------------------------------
// One warp per row of logits [BT, 96]; 3 values/lane.
__global__ __launch_bounds__(256) void loss_kernel(const float* __restrict__ logits,
                                                   const int* __restrict__ targets,
                                                   double* __restrict__ acc) {
    int warp = (blockIdx.x * blockDim.x + threadIdx.x) >> 5;
    int lane = threadIdx.x & 31;
    const float* lr = logits + (size_t)warp * V_;
    float v0 = lr[lane], v1 = lr[lane + 32], v2 = lr[lane + 64];
    float m = fmaxf(v0, fmaxf(v1, v2));
    #pragma unroll
    for (int o = 16; o; o >>= 1) m = fmaxf(m, __shfl_xor_sync(0xffffffffu, m, o));
    float se = expf(v0 - m) + expf(v1 - m) + expf(v2 - m);
    #pragma unroll
    for (int o = 16; o; o >>= 1) se += __shfl_xor_sync(0xffffffffu, se, o);

    __shared__ float part[8];
    if (lane == 0) part[threadIdx.x >> 5] = lr[targets[warp]] - m - logf(se);
    __syncthreads();
    if (threadIdx.x == 0) {
        float s = 0.f;
        #pragma unroll
        for (int i = 0; i < 8; i++) s += part[i];
        atomicAdd(acc, (double)s);
    }
}

__global__ void finalize_loss_kernel(float* out, const double* acc) {
    out[(size_t)BT_ * V_] = (float)(-(*acc) / (double)BT_);
}

// ------------------------- launcher ----------------------------------------
extern "C" void kernel_launch(void* const* d_in, const int* in_sizes, int n_in,
                              void* d_out, int out_size) {
    const int*   idx     = (const int*)  d_in[0];
    const int*   targets = (const int*)  d_in[1];
    const float* tok     = (const float*)d_in[2];
    const float* pos     = (const float*)d_in[3];
    const float* Wq      = (const float*)d_in[4];
    const float* Wk      = (const float*)d_in[5];
    const float* Wv      = (const float*)d_in[6];
    const float* Wproj   = (const float*)d_in[7];
    const float* bproj   = (const float*)d_in[8];
    const float* W1      = (const float*)d_in[9];
    const float* b1      = (const float*)d_in[10];
    const float* W2      = (const float*)d_in[11];
    const float* b2      = (const float*)d_in[12];
    const float* ln1_s   = (const float*)d_in[13];
    const float* ln1_b   = (const float*)d_in[14];
    const float* ln2_s   = (const float*)d_in[15];
    const float* ln2_b   = (const float*)d_in[16];
    const float* lnf_s   = (const float*)d_in[17];
    const float* lnf_b   = (const float*)d_in[18];
    const float* Wout    = (const float*)d_in[19];
    const float* bout    = (const float*)d_in[20];
    float* out = (float*)d_out;

    float *x, *h, *qkv, *o, *ff, *wp;
    double* lossAcc;
    cudaGetSymbolAddress((void**)&x,   g_x);
    cudaGetSymbolAddress((void**)&h,   g_h);
    cudaGetSymbolAddress((void**)&qkv, g_qkv);
    cudaGetSymbolAddress((void**)&o,   g_o);
    cudaGetSymbolAddress((void**)&ff,  g_ff);
    cudaGetSymbolAddress((void**)&wp,  g_wp);
    cudaGetSymbolAddress((void**)&lossAcc, g_loss);

    // pack QKV weights: [L][H][D][HS] -> [L][D][3D]
    {
        int total = L_ * D_ * 3 * D_;
        pack_qkv_kernel<<<(total + 255) / 256, 256>>>(Wq, Wk, Wv, wp);
    }
    // embedding
    {
        int total = BT_ * D_;
        embed_kernel<<<(total + 255) / 256, 256>>>(idx, tok, pos, x);
    }

    const int MT = BT_ / 128;  // 128 M-tiles
    for (int l = 0; l < L_; l++) {
        // LN1
        ln_kernel<<<BT_, 256>>>(x, ln1_s + l * D_, ln1_b + l * D_, h);
        // QKV: [BT,512] x [512,1536]
        sgemm_kernel<<<dim3(12, MT), 256>>>(h, wp + (size_t)l * D_ * 3 * D_,
                                            nullptr, nullptr, qkv,
                                            BT_, 3 * D_, D_, 0);
        // attention
        attn_kernel<<<dim3(T_ / 128, B_ * H_), 128>>>(qkv, o);
        // proj + bias + residual into x
        sgemm_kernel<<<dim3(4, MT), 256>>>(o, Wproj + (size_t)l * D_ * D_,
                                           bproj + l * D_, x, x,
                                           BT_, D_, D_, 3);
        // LN2
        ln_kernel<<<BT_, 256>>>(x, ln2_s + l * D_, ln2_b + l * D_, h);
        // FF1 + bias + relu
        sgemm_kernel<<<dim3(16, MT), 256>>>(h, W1 + (size_t)l * D_ * FF_,
                                            b1 + l * FF_, nullptr, ff,
                                            BT_, FF_, D_, 2);
        // FF2 + bias + residual into x
        sgemm_kernel<<<dim3(4, MT), 256>>>(ff, W2 + (size_t)l * FF_ * D_,
                                           b2 + l * D_, x, x,
                                           BT_, D_, FF_, 3);
    }

    // final LN
    ln_kernel<<<BT_, 256>>>(x, lnf_s, lnf_b, h);
    // logits: [BT,512] x [512,96] + bout -> d_out
    sgemm_kernel<<<dim3(1, MT), 256>>>(h, Wout, bout, nullptr, out,
                                       BT_, V_, D_, 1);

    // loss
    if (out_size > BT_ * V_) {
        zero_loss_kernel<<<1, 1>>>(lossAcc);
        loss_kernel<<<BT_ / 8, 256>>>(out, targets, lossAcc);
        finalize_loss_kernel<<<1, 1>>>(out, lossAcc);
    }
}

// round 3
// speedup vs baseline: 1.6066x; 1.5533x over previous
#include <cuda_runtime.h>
#include <cuda_bf16.h>
#include <math.h>
#include <stdint.h>

// ---------------------------------------------------------------------------
// MiniTransformer forward: B=16, T=1024, D=512, H=8, HS=64, L=6, FF=2048, V=96
// Output: logits [16384, 96] (fp32) followed by scalar loss.
// ---------------------------------------------------------------------------

#define B_   16
#define T_   1024
#define D_   512
#define H_   8
#define HS_  64
#define L_   6
#define FF_  2048
#define V_   96
#define BT_  (B_ * T_)

// ------------------------- device scratch (no mallocs) ---------------------
__device__ float  g_x   [BT_ * D_];        // residual stream
__device__ float  g_h   [BT_ * D_];        // LN output
__device__ float  g_qkv [BT_ * 3 * D_];    // packed q|k|v per token
__device__ float  g_o   [BT_ * D_];        // attention output (concat heads)
__device__ float  g_ff  [BT_ * FF_];       // FFN hidden
__device__ float  g_wp  [L_ * D_ * 3 * D_];// packed QKV weights [l][d][3D]
__device__ double g_loss;

// ------------------------- small kernels -----------------------------------
__global__ void zero_loss_kernel(double* a) { *a = 0.0; }

__global__ void pack_qkv_kernel(const float* __restrict__ Wq,
                                const float* __restrict__ Wk,
                                const float* __restrict__ Wv,
                                float* __restrict__ out) {
    int i = blockIdx.x * blockDim.x + threadIdx.x;       // over L*D*3D
    if (i >= L_ * D_ * 3 * D_) return;
    int c = i % (3 * D_);
    int d = (i / (3 * D_)) % D_;
    int l = i / (3 * D_ * D_);
    int sel = c >> 9;              // 0=q 1=k 2=v (512 cols each)
    int hk  = c & 511;
    int h   = hk >> 6;
    int k   = hk & 63;
    const float* W = (sel == 0) ? Wq : (sel == 1) ? Wk : Wv;
    out[i] = W[(((size_t)l * H_ + h) * D_ + d) * HS_ + k];
}

__global__ void embed_kernel(const int* __restrict__ idx,
                             const float* __restrict__ tok,
                             const float* __restrict__ pos,
                             float* __restrict__ x) {
    int i = blockIdx.x * blockDim.x + threadIdx.x;       // over BT*D
    if (i >= BT_ * D_) return;
    int d  = i & (D_ - 1);
    int bt = i >> 9;
    int t  = bt & (T_ - 1);
    x[i] = tok[(size_t)idx[bt] * D_ + d] + pos[t * D_ + d];
}

// One block per row; D=512, 256 threads, 2 elems/thread.
__global__ __launch_bounds__(256) void ln_kernel(const float* __restrict__ x,
                                                 const float* __restrict__ s,
                                                 const float* __restrict__ b,
                                                 float* __restrict__ out) {
    int row = blockIdx.x;
    int t   = threadIdx.x;
    const float* xr = x + (size_t)row * D_;
    float v0 = xr[t], v1 = xr[t + 256];

    float sum = v0 + v1;
    #pragma unroll
    for (int o = 16; o; o >>= 1) sum += __shfl_xor_sync(0xffffffffu, sum, o);
    __shared__ float red1[8], red2[8];
    if ((t & 31) == 0) red1[t >> 5] = sum;
    __syncthreads();
    float mean = 0.f;
    #pragma unroll
    for (int i = 0; i < 8; i++) mean += red1[i];
    mean *= (1.0f / D_);

    float d0 = v0 - mean, d1 = v1 - mean;
    float vs = d0 * d0 + d1 * d1;
    #pragma unroll
    for (int o = 16; o; o >>= 1) vs += __shfl_xor_sync(0xffffffffu, vs, o);
    if ((t & 31) == 0) red2[t >> 5] = vs;
    __syncthreads();
    float var = 0.f;
    #pragma unroll
    for (int i = 0; i < 8; i++) var += red2[i];
    var *= (1.0f / D_);

    float inv = rsqrtf(var + 1e-5f);
    float* orow = out + (size_t)row * D_;
    orow[t]       = d0 * inv * s[t]       + b[t];
    orow[t + 256] = d1 * inv * s[t + 256] + b[t + 256];
}

// ------------------------- TF32 tensor-core GEMM ---------------------------
// C[M,N] = A[M,K] * B[K,N]  (+bias, +relu, +residual per `mode`)
// mode: 0 = none, 1 = +bias, 2 = +bias,relu, 3 = +bias,+res
// 128x128 tile, BK=16, 256 threads = 8 warps, warp tile 64(m) x 32(n).
// mma.sync.m16n8k8 tf32, fp32 accumulate.
// Requires M % 128 == 0, K % 16 == 0. N guarded.
#define GBK 16
#define ASTR 20    // A smem stride (m-major rows of K): banks (m*20+k)%32 distinct
#define BSTR 136   // B smem stride (k-major rows of N): banks (k*8+n)%32 distinct

__device__ __forceinline__ uint32_t f2tf32(float f) {
    uint32_t r;
    asm("cvt.rna.tf32.f32 %0, %1;" : "=r"(r) : "f"(f));
    return r;
}

__device__ __forceinline__ void mma_tf32(float* d, const uint32_t* a, const uint32_t* b) {
    asm volatile(
        "mma.sync.aligned.m16n8k8.row.col.f32.tf32.tf32.f32 "
        "{%0,%1,%2,%3}, {%4,%5,%6,%7}, {%8,%9}, {%0,%1,%2,%3};"
        : "+f"(d[0]), "+f"(d[1]), "+f"(d[2]), "+f"(d[3])
        : "r"(a[0]), "r"(a[1]), "r"(a[2]), "r"(a[3]), "r"(b[0]), "r"(b[1]));
}

__global__ __launch_bounds__(256) void tgemm_kernel(
    const float* __restrict__ A, const float* __restrict__ Bm,
    const float* __restrict__ bias, const float* __restrict__ res,
    float* __restrict__ C, int M, int N, int K, int mode)
{
    __shared__ uint32_t As[2][128][ASTR];   // [m][k] as tf32 bits
    __shared__ uint32_t Bs[2][GBK][BSTR];   // [k][n] as tf32 bits

    int tid  = threadIdx.x;
    int wid  = tid >> 5;
    int lane = tid & 31;
    int grp  = lane >> 2;          // 0..7
    int tig  = lane & 3;           // 0..3
    int warp_m = (wid & 1) * 64;   // 0 or 64
    int warp_n = (wid >> 1) * 32;  // 0,32,64,96

    // A gmem loads: 128 rows x 16 cols = 512 float4; 2/thread
    int arow = tid >> 2;           // 0..63 (+64)
    int acol = (tid & 3) << 2;     // 0,4,8,12
    // B gmem loads: 16 rows x 128 cols = 512 float4; 2/thread
    int brow = tid >> 5;           // 0..7 (+8)
    int bcol = (tid & 31) << 2;    // 0..124

    const float* Ap  = A + (size_t)(blockIdx.y * 128 + arow) * K + acol;
    const float* Ap2 = Ap + (size_t)64 * K;
    int gbc = blockIdx.x * 128 + bcol;

    float acc[4][4][4];
    #pragma unroll
    for (int i = 0; i < 4; i++)
        #pragma unroll
        for (int j = 0; j < 4; j++)
            #pragma unroll
            for (int r = 0; r < 4; r++) acc[i][j][r] = 0.f;

    float4 pa0, pa1, pb0, pb1;

    // load stage 0 into regs
    pa0 = *(const float4*)(Ap);
    pa1 = *(const float4*)(Ap2);
    {
        const float* Bp0 = Bm + (size_t)brow * N;
        const float* Bp1 = Bm + (size_t)(brow + 8) * N;
        if (gbc + 3 < N) {
            pb0 = *(const float4*)(Bp0 + gbc);
            pb1 = *(const float4*)(Bp1 + gbc);
        } else {
            pb0 = make_float4(0.f, 0.f, 0.f, 0.f);
            pb1 = make_float4(0.f, 0.f, 0.f, 0.f);
            if (gbc + 0 < N) { pb0.x = Bp0[gbc + 0]; pb1.x = Bp1[gbc + 0]; }
            if (gbc + 1 < N) { pb0.y = Bp0[gbc + 1]; pb1.y = Bp1[gbc + 1]; }
            if (gbc + 2 < N) { pb0.z = Bp0[gbc + 2]; pb1.z = Bp1[gbc + 2]; }
        }
    }
    // store stage 0 (cvt to tf32)
    {
        As[0][arow][acol + 0] = f2tf32(pa0.x); As[0][arow][acol + 1] = f2tf32(pa0.y);
        As[0][arow][acol + 2] = f2tf32(pa0.z); As[0][arow][acol + 3] = f2tf32(pa0.w);
        As[0][arow + 64][acol + 0] = f2tf32(pa1.x); As[0][arow + 64][acol + 1] = f2tf32(pa1.y);
        As[0][arow + 64][acol + 2] = f2tf32(pa1.z); As[0][arow + 64][acol + 3] = f2tf32(pa1.w);
        Bs[0][brow][bcol + 0] = f2tf32(pb0.x); Bs[0][brow][bcol + 1] = f2tf32(pb0.y);
        Bs[0][brow][bcol + 2] = f2tf32(pb0.z); Bs[0][brow][bcol + 3] = f2tf32(pb0.w);
        Bs[0][brow + 8][bcol + 0] = f2tf32(pb1.x); Bs[0][brow + 8][bcol + 1] = f2tf32(pb1.y);
        Bs[0][brow + 8][bcol + 2] = f2tf32(pb1.z); Bs[0][brow + 8][bcol + 3] = f2tf32(pb1.w);
    }
    __syncthreads();

    int nstage = K / GBK;
    int cur = 0;
    for (int s = 0; s < nstage; s++) {
        // prefetch next stage into registers
        if (s + 1 < nstage) {
            int k0 = (s + 1) * GBK;
            pa0 = *(const float4*)(Ap + k0);
            pa1 = *(const float4*)(Ap2 + k0);
            const float* Bp0 = Bm + (size_t)(k0 + brow) * N;
            const float* Bp1 = Bm + (size_t)(k0 + brow + 8) * N;
            if (gbc + 3 < N) {
                pb0 = *(const float4*)(Bp0 + gbc);
                pb1 = *(const float4*)(Bp1 + gbc);
            } else {
                pb0 = make_float4(0.f, 0.f, 0.f, 0.f);
                pb1 = make_float4(0.f, 0.f, 0.f, 0.f);
                if (gbc + 0 < N) { pb0.x = Bp0[gbc + 0]; pb1.x = Bp1[gbc + 0]; }
                if (gbc + 1 < N) { pb0.y = Bp0[gbc + 1]; pb1.y = Bp1[gbc + 1]; }
                if (gbc + 2 < N) { pb0.z = Bp0[gbc + 2]; pb1.z = Bp1[gbc + 2]; }
            }
        }

        // compute: 2 k8-steps, 4 m-subtiles x 4 n-subtiles
        #pragma unroll
        for (int ks = 0; ks < 2; ks++) {
            int k0 = ks * 8;
            uint32_t af[4][4];
            #pragma unroll
            for (int i = 0; i < 4; i++) {
                int mrow = warp_m + i * 16 + grp;
                af[i][0] = As[cur][mrow][k0 + tig];
                af[i][1] = As[cur][mrow + 8][k0 + tig];
                af[i][2] = As[cur][mrow][k0 + tig + 4];
                af[i][3] = As[cur][mrow + 8][k0 + tig + 4];
            }
            uint32_t bf[4][2];
            #pragma unroll
            for (int j = 0; j < 4; j++) {
                int ncol = warp_n + j * 8 + grp;
                bf[j][0] = Bs[cur][k0 + tig][ncol];
                bf[j][1] = Bs[cur][k0 + tig + 4][ncol];
            }
            #pragma unroll
            for (int i = 0; i < 4; i++)
                #pragma unroll
                for (int j = 0; j < 4; j++)
                    mma_tf32(acc[i][j], af[i], bf[j]);
        }

        // store prefetched regs into the other buffer
        if (s + 1 < nstage) {
            int nxt = cur ^ 1;
            As[nxt][arow][acol + 0] = f2tf32(pa0.x); As[nxt][arow][acol + 1] = f2tf32(pa0.y);
            As[nxt][arow][acol + 2] = f2tf32(pa0.z); As[nxt][arow][acol + 3] = f2tf32(pa0.w);
            As[nxt][arow + 64][acol + 0] = f2tf32(pa1.x); As[nxt][arow + 64][acol + 1] = f2tf32(pa1.y);
            As[nxt][arow + 64][acol + 2] = f2tf32(pa1.z); As[nxt][arow + 64][acol + 3] = f2tf32(pa1.w);
            Bs[nxt][brow][bcol + 0] = f2tf32(pb0.x); Bs[nxt][brow][bcol + 1] = f2tf32(pb0.y);
            Bs[nxt][brow][bcol + 2] = f2tf32(pb0.z); Bs[nxt][brow][bcol + 3] = f2tf32(pb0.w);
            Bs[nxt][brow + 8][bcol + 0] = f2tf32(pb1.x); Bs[nxt][brow + 8][bcol + 1] = f2tf32(pb1.y);
            Bs[nxt][brow + 8][bcol + 2] = f2tf32(pb1.z); Bs[nxt][brow + 8][bcol + 3] = f2tf32(pb1.w);
            __syncthreads();
            cur = nxt;
        }
    }

    // epilogue
    #pragma unroll
    for (int i = 0; i < 4; i++) {
        int row0 = blockIdx.y * 128 + warp_m + i * 16 + grp;
        #pragma unroll
        for (int j = 0; j < 4; j++) {
            int col = blockIdx.x * 128 + warp_n + j * 8 + 2 * tig;
            if (col < N) {
                #pragma unroll
                for (int half = 0; half < 2; half++) {
                    int r = row0 + half * 8;
                    size_t rb = (size_t)r * N;
                    float v0 = acc[i][j][half * 2 + 0];
                    float v1 = acc[i][j][half * 2 + 1];
                    if (mode >= 1) { v0 += bias[col]; v1 += bias[col + 1]; }
                    if (mode == 2) { v0 = fmaxf(v0, 0.f); v1 = fmaxf(v1, 0.f); }
                    if (mode == 3) { v0 += res[rb + col]; v1 += res[rb + col + 1]; }
                    *(float2*)(C + rb + col) = make_float2(v0, v1);
                }
            }
        }
    }
}

// ------------------------- flash attention ---------------------------------
// QKV [BT, 1536] per-token q|k|v; heads at h*64 within each 512 chunk.
// grid: (T/128, B*H), block 256 threads: 2 threads per query (each 32 dims).
#define AKT 32
#define KSTR 68

__global__ __launch_bounds__(256) void attn_kernel(const float* __restrict__ QKV,
                                                   float* __restrict__ O) {
    int b = blockIdx.y >> 3;
    int h = blockIdx.y & 7;
    int tid = threadIdx.x;
    int ql   = tid >> 1;            // 0..127 local query
    int half = tid & 1;             // dim half
    int q_idx = blockIdx.x * 128 + ql;
    const float scale = 0.04419417382415922f;  // 1/sqrt(512)

    const float* qrow = QKV + ((size_t)(b * T_ + q_idx)) * (3 * D_) + h * HS_ + half * 32;
    float q[32];
    #pragma unroll
    for (int d = 0; d < 32; d++) q[d] = qrow[d] * scale;
    float o[32];
    #pragma unroll
    for (int d = 0; d < 32; d++) o[d] = 0.f;
    float m = -1e30f, l = 0.f;

    __shared__ float Ks[AKT][KSTR];
    __shared__ float Vs[AKT][KSTR];

    int kend = blockIdx.x * 128 + 128;
    for (int k0 = 0; k0 < kend; k0 += AKT) {
        __syncthreads();
        for (int i = tid; i < AKT * (HS_ / 4); i += 256) {
            int r = i >> 4, c = (i & 15) << 2;
            const float* base = QKV + ((size_t)(b * T_ + k0 + r)) * (3 * D_) + h * HS_ + c;
            *(float4*)&Ks[r][c] = *(const float4*)(base + D_);
            *(float4*)&Vs[r][c] = *(const float4*)(base + 2 * D_);
        }
        __syncthreads();

        float s[AKT];
        float mnew = m;
        #pragma unroll
        for (int j = 0; j < AKT; j++) {
            float acc = 0.f;
            const float* kr = &Ks[j][half * 32];
            #pragma unroll
            for (int d = 0; d < 32; d++) acc += q[d] * kr[d];
            acc += __shfl_xor_sync(0xffffffffu, acc, 1);
            s[j] = (k0 + j <= q_idx) ? acc : -1e30f;
            mnew = fmaxf(mnew, s[j]);
        }
        float corr = __expf(m - mnew);
        l *= corr;
        #pragma unroll
        for (int d = 0; d < 32; d++) o[d] *= corr;
        #pragma unroll
        for (int j = 0; j < AKT; j++) {
            float p = __expf(s[j] - mnew);
            l += p;
            const float* vr = &Vs[j][half * 32];
            #pragma unroll
            for (int d = 0; d < 32; d++) o[d] += p * vr[d];
        }
        m = mnew;
    }

    float inv = 1.f / l;
    float* orow = O + ((size_t)(b * T_ + q_idx)) * D_ + h * HS_ + half * 32;
    #pragma unroll
    for (int d = 0; d < 32; d++) orow[d] = o[d] * inv;
}

// ------------------------- loss --------------------------------------------
// One warp per row of logits [BT, 96]; 3 values/lane.
__global__ __launch_bounds__(256) void loss_kernel(const float* __restrict__ logits,
                                                   const int* __restrict__ targets,
                                                   double* __restrict__ acc) {
    int warp = (blockIdx.x * blockDim.x + threadIdx.x) >> 5;
    int lane = threadIdx.x & 31;
    const float* lr = logits + (size_t)warp * V_;
    float v0 = lr[lane], v1 = lr[lane + 32], v2 = lr[lane + 64];
    float m = fmaxf(v0, fmaxf(v1, v2));
    #pragma unroll
    for (int o = 16; o; o >>= 1) m = fmaxf(m, __shfl_xor_sync(0xffffffffu, m, o));
    float se = expf(v0 - m) + expf(v1 - m) + expf(v2 - m);
    #pragma unroll
    for (int o = 16; o; o >>= 1) se += __shfl_xor_sync(0xffffffffu, se, o);

    __shared__ float part[8];
    if (lane == 0) part[threadIdx.x >> 5] = lr[targets[warp]] - m - logf(se);
    __syncthreads();
    if (threadIdx.x == 0) {
        float s = 0.f;
        #pragma unroll
        for (int i = 0; i < 8; i++) s += part[i];
        atomicAdd(acc, (double)s);
    }
}

__global__ void finalize_loss_kernel(float* out, const double* acc) {
    out[(size_t)BT_ * V_] = (float)(-(*acc) / (double)BT_);
}

// ------------------------- launcher ----------------------------------------
extern "C" void kernel_launch(void* const* d_in, const int* in_sizes, int n_in,
                              void* d_out, int out_size) {
    const int*   idx     = (const int*)  d_in[0];
    const int*   targets = (const int*)  d_in[1];
    const float* tok     = (const float*)d_in[2];
    const float* pos     = (const float*)d_in[3];
    const float* Wq      = (const float*)d_in[4];
    const float* Wk      = (const float*)d_in[5];
    const float* Wv      = (const float*)d_in[6];
    const float* Wproj   = (const float*)d_in[7];
    const float* bproj   = (const float*)d_in[8];
    const float* W1      = (const float*)d_in[9];
    const float* b1      = (const float*)d_in[10];
    const float* W2      = (const float*)d_in[11];
    const float* b2      = (const float*)d_in[12];
    const float* ln1_s   = (const float*)d_in[13];
    const float* ln1_b   = (const float*)d_in[14];
    const float* ln2_s   = (const float*)d_in[15];
    const float* ln2_b   = (const float*)d_in[16];
    const float* lnf_s   = (const float*)d_in[17];
    const float* lnf_b   = (const float*)d_in[18];
    const float* Wout    = (const float*)d_in[19];
    const float* bout    = (const float*)d_in[20];
    float* out = (float*)d_out;

    float *x, *h, *qkv, *o, *ff, *wp;
    double* lossAcc;
    cudaGetSymbolAddress((void**)&x,   g_x);
    cudaGetSymbolAddress((void**)&h,   g_h);
    cudaGetSymbolAddress((void**)&qkv, g_qkv);
    cudaGetSymbolAddress((void**)&o,   g_o);
    cudaGetSymbolAddress((void**)&ff,  g_ff);
    cudaGetSymbolAddress((void**)&wp,  g_wp);
    cudaGetSymbolAddress((void**)&lossAcc, g_loss);

    // pack QKV weights: [L][H][D][HS] -> [L][D][3D]
    {
        int total = L_ * D_ * 3 * D_;
        pack_qkv_kernel<<<(total + 255) / 256, 256>>>(Wq, Wk, Wv, wp);
    }
    // embedding
    {
        int total = BT_ * D_;
        embed_kernel<<<(total + 255) / 256, 256>>>(idx, tok, pos, x);
    }

    const int MT = BT_ / 128;  // 128 M-tiles
    for (int l = 0; l < L_; l++) {
        // LN1
        ln_kernel<<<BT_, 256>>>(x, ln1_s + l * D_, ln1_b + l * D_, h);
        // QKV: [BT,512] x [512,1536]
        tgemm_kernel<<<dim3(12, MT), 256>>>(h, wp + (size_t)l * D_ * 3 * D_,
                                            nullptr, nullptr, qkv,
                                            BT_, 3 * D_, D_, 0);
        // attention
        attn_kernel<<<dim3(T_ / 128, B_ * H_), 256>>>(qkv, o);
        // proj + bias + residual into x
        tgemm_kernel<<<dim3(4, MT), 256>>>(o, Wproj + (size_t)l * D_ * D_,
                                           bproj + l * D_, x, x,
                                           BT_, D_, D_, 3);
        // LN2
        ln_kernel<<<BT_, 256>>>(x, ln2_s + l * D_, ln2_b + l * D_, h);
        // FF1 + bias + relu
        tgemm_kernel<<<dim3(16, MT), 256>>>(h, W1 + (size_t)l * D_ * FF_,
                                            b1 + l * FF_, nullptr, ff,
                                            BT_, FF_, D_, 2);
        // FF2 + bias + residual into x
        tgemm_kernel<<<dim3(4, MT), 256>>>(ff, W2 + (size_t)l * FF_ * D_,
                                           b2 + l * D_, x, x,
                                           BT_, D_, FF_, 3);
    }

    // final LN
    ln_kernel<<<BT_, 256>>>(x, lnf_s, lnf_b, h);
    // logits: [BT,512] x [512,96] + bout -> d_out
    tgemm_kernel<<<dim3(1, MT), 256>>>(h, Wout, bout, nullptr, out,
                                       BT_, V_, D_, 1);

    // loss
    if (out_size > BT_ * V_) {
        zero_loss_kernel<<<1, 1>>>(lossAcc);
        loss_kernel<<<BT_ / 8, 256>>>(out, targets, lossAcc);
        finalize_loss_kernel<<<1, 1>>>(out, lossAcc);
    }
}